// round 1
// baseline (speedup 1.0000x reference)
#include <cuda_runtime.h>
#include <cstdint>

#define N_NODES 100000
#define N_EDGES 1600000
#define DIM     128

// Scratch (no cudaMalloc allowed): 51.2 MB accumulator + degree + norm
__device__ float g_agg[(size_t)N_NODES * DIM];
__device__ int   g_deg[N_NODES];
__device__ float g_norm[N_NODES];

// ---------------------------------------------------------------------------
// Kernel 1: zero agg (+ deg)
// ---------------------------------------------------------------------------
__global__ void zero_kernel() {
    int i = blockIdx.x * blockDim.x + threadIdx.x;
    int n4 = N_NODES * DIM / 4;  // 3.2M float4
    if (i < n4) {
        ((float4*)g_agg)[i] = make_float4(0.f, 0.f, 0.f, 0.f);
    }
    if (i < N_NODES) g_deg[i] = 0;
}

// ---------------------------------------------------------------------------
// Kernel 2: in-degree histogram
// ---------------------------------------------------------------------------
__global__ void deg_kernel(const int* __restrict__ edge_dst) {
    int i = blockIdx.x * blockDim.x + threadIdx.x;
    if (i < N_EDGES) {
        atomicAdd(&g_deg[edge_dst[i]], 1);
    }
}

// ---------------------------------------------------------------------------
// Kernel 3: norm = deg^{-1/2}, clamped
// ---------------------------------------------------------------------------
__global__ void norm_kernel() {
    int i = blockIdx.x * blockDim.x + threadIdx.x;
    if (i < N_NODES) {
        int d = g_deg[i];
        g_norm[i] = rsqrtf((float)(d > 0 ? d : 1));
    }
}

// ---------------------------------------------------------------------------
// Kernel 4: scatter-add  agg[dst] += h[src] * norm[src]
// One warp per edge; lane l handles float4 l (32*4 = 128 floats).
// Vectorized no-return atomic (red.global.add.v4.f32, sm_90+).
// ---------------------------------------------------------------------------
__global__ void scatter_kernel(const float* __restrict__ h,
                               const int*   __restrict__ edge_src,
                               const int*   __restrict__ edge_dst) {
    int gtid = blockIdx.x * blockDim.x + threadIdx.x;
    int e    = gtid >> 5;
    int lane = threadIdx.x & 31;
    if (e >= N_EDGES) return;

    int s = __ldg(&edge_src[e]);
    int d = __ldg(&edge_dst[e]);
    float nrm = g_norm[s];

    float4 v = __ldg(&((const float4*)h)[(size_t)s * 32 + lane]);
    v.x *= nrm; v.y *= nrm; v.z *= nrm; v.w *= nrm;

    float* p = &g_agg[(size_t)d * DIM + lane * 4];
    asm volatile("red.global.add.v4.f32 [%0], {%1, %2, %3, %4};"
                 :: "l"(p), "f"(v.x), "f"(v.y), "f"(v.z), "f"(v.w)
                 : "memory");
}

// ---------------------------------------------------------------------------
// Kernel 5: out = (agg * norm) @ W^T + b
//   W is [OUT=128, IN=128] row-major; out[r][n] = sum_k A[r][k]*W[n][k] + b[n]
// Block: 256 threads, computes BM=64 rows x 128 cols.
// Thread grid 16x16; each thread: 4 rows x 8 cols register tile.
// K staged in chunks of 32; W chunk transposed into smem as sW[k][n].
// ---------------------------------------------------------------------------
#define BM 64

__global__ __launch_bounds__(256, 4)
void gemm_kernel(const float* __restrict__ W,
                 const float* __restrict__ bias,
                 float*       __restrict__ out) {
    __shared__ float sW[32][132];   // [k][n], pad 132 -> 528B row (16B aligned)
    __shared__ float sA[BM][33];    // [r][k]

    int tid = threadIdx.x;
    int tx = tid & 15;              // col group 0..15 (8 cols each)
    int ty = tid >> 4;              // row group 0..15 (4 rows each)
    int row0 = blockIdx.x * BM;

    float acc[4][8];
#pragma unroll
    for (int i = 0; i < 4; i++)
#pragma unroll
        for (int j = 0; j < 8; j++) acc[i][j] = 0.f;

    for (int k0 = 0; k0 < DIM; k0 += 32) {
        // --- stage W chunk: sW[k][n] = W[n][k0+k], 128n x 32k ---
        // 1024 float4 loads, 4 per thread
#pragma unroll
        for (int t = tid; t < 1024; t += 256) {
            int n  = t >> 3;             // 0..127
            int kq = (t & 7) << 2;       // 0,4,...,28
            float4 w4 = __ldg(&((const float4*)W)[(n * DIM + k0 + kq) >> 2]);
            sW[kq + 0][n] = w4.x;
            sW[kq + 1][n] = w4.y;
            sW[kq + 2][n] = w4.z;
            sW[kq + 3][n] = w4.w;
        }
        // --- stage A chunk: sA[r][k] = agg[row][k0+k] * norm[row] ---
        // 512 float4 loads, 2 per thread
#pragma unroll
        for (int t = tid; t < 512; t += 256) {
            int r  = t >> 3;             // 0..63
            int kq = (t & 7) << 2;
            int row = row0 + r;
            float4 a4 = make_float4(0.f, 0.f, 0.f, 0.f);
            float nr = 0.f;
            if (row < N_NODES) {
                a4 = ((const float4*)g_agg)[((size_t)row * DIM + k0 + kq) >> 2];
                nr = g_norm[row];
            }
            sA[r][kq + 0] = a4.x * nr;
            sA[r][kq + 1] = a4.y * nr;
            sA[r][kq + 2] = a4.z * nr;
            sA[r][kq + 3] = a4.w * nr;
        }
        __syncthreads();

#pragma unroll
        for (int k = 0; k < 32; k++) {
            float a[4];
#pragma unroll
            for (int i = 0; i < 4; i++) a[i] = sA[ty * 4 + i][k];
            float4 b0 = *(const float4*)&sW[k][tx * 8];
            float4 b1 = *(const float4*)&sW[k][tx * 8 + 4];
            float bb[8] = {b0.x, b0.y, b0.z, b0.w, b1.x, b1.y, b1.z, b1.w};
#pragma unroll
            for (int i = 0; i < 4; i++)
#pragma unroll
                for (int j = 0; j < 8; j++)
                    acc[i][j] += a[i] * bb[j];
        }
        __syncthreads();
    }

    // epilogue: add bias, store
    float4 bv0 = __ldg(&((const float4*)bias)[tx * 2]);
    float4 bv1 = __ldg(&((const float4*)bias)[tx * 2 + 1]);
#pragma unroll
    for (int i = 0; i < 4; i++) {
        int row = row0 + ty * 4 + i;
        if (row >= N_NODES) continue;
        float4 o0 = make_float4(acc[i][0] + bv0.x, acc[i][1] + bv0.y,
                                acc[i][2] + bv0.z, acc[i][3] + bv0.w);
        float4 o1 = make_float4(acc[i][4] + bv1.x, acc[i][5] + bv1.y,
                                acc[i][6] + bv1.z, acc[i][7] + bv1.w);
        float4* op = (float4*)&out[(size_t)row * DIM + tx * 8];
        op[0] = o0;
        op[1] = o1;
    }
}

// ---------------------------------------------------------------------------
// Launch
// inputs (metadata order): h[N*128] f32, W[128*128] f32, b[128] f32,
//                          edge_src[E] i32, edge_dst[E] i32
// output: out[N*128] f32
// ---------------------------------------------------------------------------
extern "C" void kernel_launch(void* const* d_in, const int* in_sizes, int n_in,
                              void* d_out, int out_size) {
    const float* h        = (const float*)d_in[0];
    const float* W        = (const float*)d_in[1];
    const float* b        = (const float*)d_in[2];
    const int*   edge_src = (const int*)d_in[3];
    const int*   edge_dst = (const int*)d_in[4];
    float*       out      = (float*)d_out;

    // 1. zero agg + deg
    {
        int n4 = N_NODES * DIM / 4;
        int blocks = (n4 + 255) / 256;
        zero_kernel<<<blocks, 256>>>();
    }
    // 2. degree
    deg_kernel<<<(N_EDGES + 255) / 256, 256>>>(edge_dst);
    // 3. norm
    norm_kernel<<<(N_NODES + 255) / 256, 256>>>();
    // 4. scatter (1 warp per edge)
    {
        long long threads = (long long)N_EDGES * 32;
        int blocks = (int)((threads + 255) / 256);
        scatter_kernel<<<blocks, 256>>>(h, edge_src, edge_dst);
    }
    // 5. GEMM + bias
    gemm_kernel<<<(N_NODES + BM - 1) / BM, 256>>>(W, b, out);
}

// round 3
// speedup vs baseline: 1.7214x; 1.7214x over previous
#include <cuda_runtime.h>
#include <cstdint>

#define N_NODES 100000
#define N_EDGES 1600000
#define DIM     128
#define SCAN_BS 1024
#define NSCAN   ((N_NODES + SCAN_BS - 1) / SCAN_BS)   // 98

// Scratch (no cudaMalloc allowed)
__device__ float g_agg[(size_t)N_NODES * DIM];   // normalized aggregate (aggn)
__device__ int   g_deg[N_NODES];
__device__ float g_norm[N_NODES];
__device__ int   g_part[N_NODES];                 // per-block exclusive scan of deg
__device__ int   g_bsum[NSCAN];                   // per-block totals
__device__ int   g_boff[NSCAN];                   // exclusive scan of block totals
__device__ int   g_row_start[N_NODES + 1];        // CSR row pointers
__device__ int   g_cursor[N_NODES];               // atomic fill cursors
__device__ int   g_sorted_src[N_EDGES];           // src ids grouped by dst

// ---------------------------------------------------------------------------
// 1. zero degree counters
// ---------------------------------------------------------------------------
__global__ void zero_deg_kernel() {
    int i = blockIdx.x * blockDim.x + threadIdx.x;
    if (i < N_NODES) g_deg[i] = 0;
}

// ---------------------------------------------------------------------------
// 2. in-degree histogram
// ---------------------------------------------------------------------------
__global__ void deg_kernel(const int* __restrict__ edge_dst) {
    int i = blockIdx.x * blockDim.x + threadIdx.x;
    if (i < N_EDGES) atomicAdd(&g_deg[edge_dst[i]], 1);
}

// ---------------------------------------------------------------------------
// 3a. per-block exclusive scan of deg (1024/block, Hillis-Steele)
// ---------------------------------------------------------------------------
__global__ __launch_bounds__(SCAN_BS)
void scan_block_kernel() {
    __shared__ int s[SCAN_BS];
    int tid = threadIdx.x;
    int gi  = blockIdx.x * SCAN_BS + tid;
    int v = (gi < N_NODES) ? g_deg[gi] : 0;
    s[tid] = v;
    __syncthreads();
#pragma unroll
    for (int off = 1; off < SCAN_BS; off <<= 1) {
        int t = (tid >= off) ? s[tid - off] : 0;
        __syncthreads();
        s[tid] += t;
        __syncthreads();
    }
    // inclusive -> exclusive
    if (gi < N_NODES) g_part[gi] = s[tid] - v;
    if (tid == SCAN_BS - 1) g_bsum[blockIdx.x] = s[tid];
}

// ---------------------------------------------------------------------------
// 3b. scan the 98 block sums (one block)
// ---------------------------------------------------------------------------
__global__ void scan_top_kernel() {
    __shared__ int s[128];
    int tid = threadIdx.x;
    int v = (tid < NSCAN) ? g_bsum[tid] : 0;
    s[tid] = v;
    __syncthreads();
#pragma unroll
    for (int off = 1; off < 128; off <<= 1) {
        int t = (tid >= off) ? s[tid - off] : 0;
        __syncthreads();
        s[tid] += t;
        __syncthreads();
    }
    if (tid < NSCAN) g_boff[tid] = s[tid] - v;
}

// ---------------------------------------------------------------------------
// 3c. finalize row_start + cursor + norm
// ---------------------------------------------------------------------------
__global__ void finalize_kernel() {
    int i = blockIdx.x * blockDim.x + threadIdx.x;
    if (i < N_NODES) {
        int rs = g_part[i] + g_boff[i / SCAN_BS];
        g_row_start[i] = rs;
        g_cursor[i]    = rs;
        int d = g_deg[i];
        g_norm[i] = rsqrtf((float)(d > 0 ? d : 1));
    }
    if (i == 0) g_row_start[N_NODES] = N_EDGES;
}

// ---------------------------------------------------------------------------
// 4. bucket edges by dst (counting-sort scatter of src ids)
// ---------------------------------------------------------------------------
__global__ void csr_scatter_kernel(const int* __restrict__ edge_src,
                                   const int* __restrict__ edge_dst) {
    int e = blockIdx.x * blockDim.x + threadIdx.x;
    if (e < N_EDGES) {
        int d = edge_dst[e];
        int pos = atomicAdd(&g_cursor[d], 1);
        g_sorted_src[pos] = edge_src[e];
    }
}

// ---------------------------------------------------------------------------
// 5. gather-aggregate: one warp per node, no atomics
//    aggn[dst] = norm[dst] * sum_{src in N(dst)} norm[src] * h[src]
// ---------------------------------------------------------------------------
__global__ __launch_bounds__(256)
void gather_kernel(const float* __restrict__ h) {
    int warp = (blockIdx.x * blockDim.x + threadIdx.x) >> 5;
    int lane = threadIdx.x & 31;
    if (warp >= N_NODES) return;

    int start = __ldg(&g_row_start[warp]);
    int end   = __ldg(&g_row_start[warp + 1]);

    const float4* h4 = (const float4*)h;
    float4 acc0 = make_float4(0.f, 0.f, 0.f, 0.f);
    float4 acc1 = make_float4(0.f, 0.f, 0.f, 0.f);

    int e = start;
    for (; e + 1 < end; e += 2) {
        int s0 = __ldg(&g_sorted_src[e]);
        int s1 = __ldg(&g_sorted_src[e + 1]);
        float n0 = __ldg(&g_norm[s0]);
        float n1 = __ldg(&g_norm[s1]);
        float4 v0 = __ldg(&h4[(size_t)s0 * 32 + lane]);
        float4 v1 = __ldg(&h4[(size_t)s1 * 32 + lane]);
        acc0.x += v0.x * n0; acc0.y += v0.y * n0;
        acc0.z += v0.z * n0; acc0.w += v0.w * n0;
        acc1.x += v1.x * n1; acc1.y += v1.y * n1;
        acc1.z += v1.z * n1; acc1.w += v1.w * n1;
    }
    if (e < end) {
        int s0 = __ldg(&g_sorted_src[e]);
        float n0 = __ldg(&g_norm[s0]);
        float4 v0 = __ldg(&h4[(size_t)s0 * 32 + lane]);
        acc0.x += v0.x * n0; acc0.y += v0.y * n0;
        acc0.z += v0.z * n0; acc0.w += v0.w * n0;
    }

    float nd = __ldg(&g_norm[warp]);
    float4 r = make_float4((acc0.x + acc1.x) * nd, (acc0.y + acc1.y) * nd,
                           (acc0.z + acc1.z) * nd, (acc0.w + acc1.w) * nd);
    ((float4*)g_agg)[(size_t)warp * 32 + lane] = r;
}

// ---------------------------------------------------------------------------
// 6. out = aggn @ W^T + b     (aggn already carries both norms)
//    128x128 block tile, 8x8 per-thread, K chunked by 16, operands [k][.]
// ---------------------------------------------------------------------------
#define GBM 128
#define GBK 16

__global__ __launch_bounds__(256, 2)
void gemm_kernel(const float* __restrict__ W,
                 const float* __restrict__ bias,
                 float*       __restrict__ out) {
    __shared__ float sA[GBK][GBM + 4];   // [k][m]
    __shared__ float sW[GBK][DIM + 4];   // [k][n]

    int tid  = threadIdx.x;
    int tx   = tid & 15;     // col group (8 cols)
    int ty   = tid >> 4;     // row group (8 rows)
    int row0 = blockIdx.x * GBM;

    float acc[8][8];
#pragma unroll
    for (int i = 0; i < 8; i++)
#pragma unroll
        for (int j = 0; j < 8; j++) acc[i][j] = 0.f;

    for (int k0 = 0; k0 < DIM; k0 += GBK) {
        // stage W chunk transposed: sW[k][n] = W[n][k0+k] ; 512 float4 total
#pragma unroll
        for (int t = tid; t < 512; t += 256) {
            int n  = t >> 2;
            int kq = (t & 3) << 2;
            float4 w4 = __ldg(&((const float4*)W)[(n * DIM + k0 + kq) >> 2]);
            sW[kq + 0][n] = w4.x;
            sW[kq + 1][n] = w4.y;
            sW[kq + 2][n] = w4.z;
            sW[kq + 3][n] = w4.w;
        }
        // stage A chunk transposed: sA[k][m] = aggn[row0+m][k0+k]
#pragma unroll
        for (int t = tid; t < 512; t += 256) {
            int m  = t >> 2;
            int kq = (t & 3) << 2;
            int row = row0 + m;
            float4 a4 = make_float4(0.f, 0.f, 0.f, 0.f);
            if (row < N_NODES)
                a4 = ((const float4*)g_agg)[((size_t)row * DIM + k0 + kq) >> 2];
            sA[kq + 0][m] = a4.x;
            sA[kq + 1][m] = a4.y;
            sA[kq + 2][m] = a4.z;
            sA[kq + 3][m] = a4.w;
        }
        __syncthreads();

#pragma unroll
        for (int k = 0; k < GBK; k++) {
            float4 a0 = *(const float4*)&sA[k][ty * 8];
            float4 a1 = *(const float4*)&sA[k][ty * 8 + 4];
            float4 b0 = *(const float4*)&sW[k][tx * 8];
            float4 b1 = *(const float4*)&sW[k][tx * 8 + 4];
            float av[8] = {a0.x, a0.y, a0.z, a0.w, a1.x, a1.y, a1.z, a1.w};
            float bv[8] = {b0.x, b0.y, b0.z, b0.w, b1.x, b1.y, b1.z, b1.w};
#pragma unroll
            for (int i = 0; i < 8; i++)
#pragma unroll
                for (int j = 0; j < 8; j++)
                    acc[i][j] += av[i] * bv[j];
        }
        __syncthreads();
    }

    // epilogue
    float4 bv0 = __ldg(&((const float4*)bias)[tx * 2]);
    float4 bv1 = __ldg(&((const float4*)bias)[tx * 2 + 1]);
#pragma unroll
    for (int i = 0; i < 8; i++) {
        int row = row0 + ty * 8 + i;
        if (row >= N_NODES) continue;
        float4 o0 = make_float4(acc[i][0] + bv0.x, acc[i][1] + bv0.y,
                                acc[i][2] + bv0.z, acc[i][3] + bv0.w);
        float4 o1 = make_float4(acc[i][4] + bv1.x, acc[i][5] + bv1.y,
                                acc[i][6] + bv1.z, acc[i][7] + bv1.w);
        float4* op = (float4*)&out[(size_t)row * DIM + tx * 8];
        op[0] = o0;
        op[1] = o1;
    }
}

// ---------------------------------------------------------------------------
// Launch
// ---------------------------------------------------------------------------
extern "C" void kernel_launch(void* const* d_in, const int* in_sizes, int n_in,
                              void* d_out, int out_size) {
    const float* h        = (const float*)d_in[0];
    const float* W        = (const float*)d_in[1];
    const float* b        = (const float*)d_in[2];
    const int*   edge_src = (const int*)d_in[3];
    const int*   edge_dst = (const int*)d_in[4];
    float*       out      = (float*)d_out;

    zero_deg_kernel<<<(N_NODES + 255) / 256, 256>>>();
    deg_kernel<<<(N_EDGES + 255) / 256, 256>>>(edge_dst);
    scan_block_kernel<<<NSCAN, SCAN_BS>>>();
    scan_top_kernel<<<1, 128>>>();
    finalize_kernel<<<(N_NODES + 255) / 256, 256>>>();
    csr_scatter_kernel<<<(N_EDGES + 255) / 256, 256>>>(edge_src, edge_dst);

    {   // one warp per node
        int warps_per_block = 256 / 32;
        int blocks = (N_NODES + warps_per_block - 1) / warps_per_block;
        gather_kernel<<<blocks, 256>>>(h);
    }
    gemm_kernel<<<(N_NODES + GBM - 1) / GBM, 256>>>(W, b, out);
}

// round 6
// speedup vs baseline: 2.1922x; 1.2735x over previous
#include <cuda_runtime.h>
#include <cstdint>

#define N_NODES 100000
#define N_EDGES 1600000
#define DIM     128
#define SCAN_BS 1024
#define NSCAN   ((N_NODES + SCAN_BS - 1) / SCAN_BS)   // 98

// Scratch (no cudaMalloc allowed)
__device__ float g_agg[(size_t)N_NODES * DIM];   // normalized aggregate
__device__ int   g_deg[N_NODES];
__device__ float g_norm[N_NODES];
__device__ int   g_part[N_NODES];
__device__ int   g_bsum[NSCAN];
__device__ int   g_row_start[N_NODES + 1];
__device__ int   g_cursor[N_NODES];
__device__ int   g_sorted_src[N_EDGES];

// ---------------------------------------------------------------------------
// 1. zero degree counters
// ---------------------------------------------------------------------------
__global__ void zero_deg_kernel() {
    int i = blockIdx.x * blockDim.x + threadIdx.x;
    if (i < N_NODES) g_deg[i] = 0;
}

// ---------------------------------------------------------------------------
// 2. in-degree histogram
// ---------------------------------------------------------------------------
__global__ void deg_kernel(const int* __restrict__ edge_dst) {
    int i = blockIdx.x * blockDim.x + threadIdx.x;
    if (i < N_EDGES) atomicAdd(&g_deg[edge_dst[i]], 1);
}

// ---------------------------------------------------------------------------
// 3a. per-block exclusive scan of deg
// ---------------------------------------------------------------------------
__global__ __launch_bounds__(SCAN_BS)
void scan_block_kernel() {
    __shared__ int s[SCAN_BS];
    int tid = threadIdx.x;
    int gi  = blockIdx.x * SCAN_BS + tid;
    int v = (gi < N_NODES) ? g_deg[gi] : 0;
    s[tid] = v;
    __syncthreads();
#pragma unroll
    for (int off = 1; off < SCAN_BS; off <<= 1) {
        int t = (tid >= off) ? s[tid - off] : 0;
        __syncthreads();
        s[tid] += t;
        __syncthreads();
    }
    if (gi < N_NODES) g_part[gi] = s[tid] - v;
    if (tid == SCAN_BS - 1) g_bsum[blockIdx.x] = s[tid];
}

// ---------------------------------------------------------------------------
// 3b. finalize: re-scan the 98 block sums locally, build row_start/cursor/norm
// ---------------------------------------------------------------------------
__global__ __launch_bounds__(256)
void finalize_kernel() {
    __shared__ int ss[128];   // inclusive scan of g_bsum
    int tid = threadIdx.x;
    if (tid < 128) ss[tid] = (tid < NSCAN) ? g_bsum[tid] : 0;
    __syncthreads();
#pragma unroll
    for (int off = 1; off < 128; off <<= 1) {
        int t = (tid < 128 && tid >= off) ? ss[tid - off] : 0;
        __syncthreads();
        if (tid < 128) ss[tid] += t;
        __syncthreads();
    }
    int i = blockIdx.x * blockDim.x + tid;
    if (i < N_NODES) {
        int reg = i / SCAN_BS;
        int boff = (reg == 0) ? 0 : ss[reg - 1];
        int rs = g_part[i] + boff;
        g_row_start[i] = rs;
        g_cursor[i]    = rs;
        int d = g_deg[i];
        g_norm[i] = rsqrtf((float)(d > 0 ? d : 1));
    }
    if (i == 0) g_row_start[N_NODES] = N_EDGES;
}

// ---------------------------------------------------------------------------
// 4. bucket edges by dst
// ---------------------------------------------------------------------------
__global__ void csr_scatter_kernel(const int* __restrict__ edge_src,
                                   const int* __restrict__ edge_dst) {
    int e = blockIdx.x * blockDim.x + threadIdx.x;
    if (e < N_EDGES) {
        int d = edge_dst[e];
        int pos = atomicAdd(&g_cursor[d], 1);
        g_sorted_src[pos] = edge_src[e];
    }
}

// ---------------------------------------------------------------------------
// 5. gather-aggregate: one warp per node, no atomics
// ---------------------------------------------------------------------------
__global__ __launch_bounds__(256)
void gather_kernel(const float* __restrict__ h) {
    int warp = (blockIdx.x * blockDim.x + threadIdx.x) >> 5;
    int lane = threadIdx.x & 31;
    if (warp >= N_NODES) return;

    int start = __ldg(&g_row_start[warp]);
    int end   = __ldg(&g_row_start[warp + 1]);

    const float4* h4 = (const float4*)h;
    float4 acc0 = make_float4(0.f, 0.f, 0.f, 0.f);
    float4 acc1 = make_float4(0.f, 0.f, 0.f, 0.f);

    int e = start;
    for (; e + 1 < end; e += 2) {
        int s0 = __ldg(&g_sorted_src[e]);
        int s1 = __ldg(&g_sorted_src[e + 1]);
        float n0 = __ldg(&g_norm[s0]);
        float n1 = __ldg(&g_norm[s1]);
        float4 v0 = __ldg(&h4[(size_t)s0 * 32 + lane]);
        float4 v1 = __ldg(&h4[(size_t)s1 * 32 + lane]);
        acc0.x += v0.x * n0; acc0.y += v0.y * n0;
        acc0.z += v0.z * n0; acc0.w += v0.w * n0;
        acc1.x += v1.x * n1; acc1.y += v1.y * n1;
        acc1.z += v1.z * n1; acc1.w += v1.w * n1;
    }
    if (e < end) {
        int s0 = __ldg(&g_sorted_src[e]);
        float n0 = __ldg(&g_norm[s0]);
        float4 v0 = __ldg(&h4[(size_t)s0 * 32 + lane]);
        acc0.x += v0.x * n0; acc0.y += v0.y * n0;
        acc0.z += v0.z * n0; acc0.w += v0.w * n0;
    }

    float nd = __ldg(&g_norm[warp]);
    float4 r = make_float4((acc0.x + acc1.x) * nd, (acc0.y + acc1.y) * nd,
                           (acc0.z + acc1.z) * nd, (acc0.w + acc1.w) * nd);
    ((float4*)g_agg)[(size_t)warp * 32 + lane] = r;
}

// ---------------------------------------------------------------------------
// 6. tf32 warp-MMA GEMM: out = aggn @ W^T + b
//    mma.sync.m16n8k8 (plain PTX, works on compute_103).
//    Block tile 128x128, 8 warps (4m x 2n), warp tile 32x64.
//    sW [n][k] stride 132 words, sA [m][k-chunk 32] stride 36 words:
//    fragment word-address % 32 == lane  -> bank-conflict-free.
// ---------------------------------------------------------------------------
#define SW_STRIDE 132
#define SA_STRIDE 36
#define SMEM_W_WORDS (128 * SW_STRIDE)           // 16896
#define SMEM_A_WORDS (128 * SA_STRIDE)           // 4608
#define SMEM_SZ ((SMEM_W_WORDS + SMEM_A_WORDS) * 4)   // 86016 B

__device__ __forceinline__ uint32_t f2tf32(float f) {
    uint32_t r;
    asm("cvt.rna.tf32.f32 %0, %1;" : "=r"(r) : "f"(f));
    return r;
}

__global__ __launch_bounds__(256)
void mma_gemm_kernel(const float* __restrict__ W,
                     const float* __restrict__ bias,
                     float*       __restrict__ out) {
    extern __shared__ uint32_t sm[];
    uint32_t* sW = sm;                  // [n][k], tf32 bits
    uint32_t* sA = sm + SMEM_W_WORDS;   // [m][k-chunk], tf32 bits

    int tid  = threadIdx.x;
    int lane = tid & 31;
    int warp = tid >> 5;
    int wm   = warp & 3;        // 0..3  -> m offset wm*32
    int wn   = warp >> 2;       // 0..1  -> n offset wn*64
    int row0 = blockIdx.x * 128;

    // ---- stage W (whole 128x128) as tf32 ----
    {
        const float4* W4 = (const float4*)W;
#pragma unroll
        for (int t = tid; t < 4096; t += 256) {
            int n = t >> 5;
            int q = t & 31;
            float4 w = __ldg(&W4[n * 32 + q]);
            uint32_t* p = &sW[n * SW_STRIDE + q * 4];
            p[0] = f2tf32(w.x); p[1] = f2tf32(w.y);
            p[2] = f2tf32(w.z); p[3] = f2tf32(w.w);
        }
    }

    float acc[2][8][4];
#pragma unroll
    for (int mt = 0; mt < 2; mt++)
#pragma unroll
        for (int nt = 0; nt < 8; nt++)
#pragma unroll
            for (int c = 0; c < 4; c++) acc[mt][nt][c] = 0.f;

    const float4* A4 = (const float4*)g_agg;

    for (int kc = 0; kc < DIM; kc += 32) {
        // ---- stage A chunk [128 rows x 32 cols] as tf32 ----
        __syncthreads();
#pragma unroll
        for (int t = tid; t < 1024; t += 256) {
            int m = t >> 3;
            int q = t & 7;
            int row = row0 + m;
            float4 a = make_float4(0.f, 0.f, 0.f, 0.f);
            if (row < N_NODES)
                a = __ldg(&A4[(size_t)row * 32 + (kc >> 2) + q]);
            uint32_t* p = &sA[m * SA_STRIDE + q * 4];
            p[0] = f2tf32(a.x); p[1] = f2tf32(a.y);
            p[2] = f2tf32(a.z); p[3] = f2tf32(a.w);
        }
        __syncthreads();

#pragma unroll
        for (int ks = 0; ks < 4; ks++) {
            int k = ks * 8 + (lane & 3);
            uint32_t a[2][4];
#pragma unroll
            for (int mt = 0; mt < 2; mt++) {
                int m = wm * 32 + mt * 16 + (lane >> 2);
                a[mt][0] = sA[m * SA_STRIDE + k];
                a[mt][1] = sA[(m + 8) * SA_STRIDE + k];
                a[mt][2] = sA[m * SA_STRIDE + k + 4];
                a[mt][3] = sA[(m + 8) * SA_STRIDE + k + 4];
            }
#pragma unroll
            for (int nt = 0; nt < 8; nt++) {
                int n = wn * 64 + nt * 8 + (lane >> 2);
                uint32_t b0 = sW[n * SW_STRIDE + kc + k];
                uint32_t b1 = sW[n * SW_STRIDE + kc + k + 4];
#pragma unroll
                for (int mt = 0; mt < 2; mt++) {
                    asm volatile(
                        "mma.sync.aligned.m16n8k8.row.col.f32.tf32.tf32.f32 "
                        "{%0,%1,%2,%3}, {%4,%5,%6,%7}, {%8,%9}, {%0,%1,%2,%3};"
                        : "+f"(acc[mt][nt][0]), "+f"(acc[mt][nt][1]),
                          "+f"(acc[mt][nt][2]), "+f"(acc[mt][nt][3])
                        : "r"(a[mt][0]), "r"(a[mt][1]),
                          "r"(a[mt][2]), "r"(a[mt][3]),
                          "r"(b0), "r"(b1));
                }
            }
        }
    }

    // ---- epilogue: bias + store (float2 per fragment pair) ----
#pragma unroll
    for (int mt = 0; mt < 2; mt++) {
        int r0 = row0 + wm * 32 + mt * 16 + (lane >> 2);
        int r1 = r0 + 8;
#pragma unroll
        for (int nt = 0; nt < 8; nt++) {
            int c = wn * 64 + nt * 8 + (lane & 3) * 2;
            float2 bb = __ldg((const float2*)&bias[c]);
            if (r0 < N_NODES) {
                float2 o = make_float2(acc[mt][nt][0] + bb.x,
                                       acc[mt][nt][1] + bb.y);
                *(float2*)&out[(size_t)r0 * DIM + c] = o;
            }
            if (r1 < N_NODES) {
                float2 o = make_float2(acc[mt][nt][2] + bb.x,
                                       acc[mt][nt][3] + bb.y);
                *(float2*)&out[(size_t)r1 * DIM + c] = o;
            }
        }
    }
}

// ---------------------------------------------------------------------------
// Launch
// ---------------------------------------------------------------------------
extern "C" void kernel_launch(void* const* d_in, const int* in_sizes, int n_in,
                              void* d_out, int out_size) {
    const float* h        = (const float*)d_in[0];
    const float* W        = (const float*)d_in[1];
    const float* b        = (const float*)d_in[2];
    const int*   edge_src = (const int*)d_in[3];
    const int*   edge_dst = (const int*)d_in[4];
    float*       out      = (float*)d_out;

    zero_deg_kernel<<<(N_NODES + 255) / 256, 256>>>();
    deg_kernel<<<(N_EDGES + 255) / 256, 256>>>(edge_dst);
    scan_block_kernel<<<NSCAN, SCAN_BS>>>();
    finalize_kernel<<<(N_NODES + 255) / 256, 256>>>();
    csr_scatter_kernel<<<(N_EDGES + 255) / 256, 256>>>(edge_src, edge_dst);

    {   // one warp per node
        int blocks = (N_NODES + 7) / 8;
        gather_kernel<<<blocks, 256>>>(h);
    }

    // >48KB dynamic smem needs the attribute; idempotent, ignore rc.
    (void)cudaFuncSetAttribute(mma_gemm_kernel,
                               cudaFuncAttributeMaxDynamicSharedMemorySize,
                               SMEM_SZ);
    int tiles = (N_NODES + 127) / 128;   // 782
    mma_gemm_kernel<<<tiles, 256, SMEM_SZ>>>(W, b, out);
}